// round 17
// baseline (speedup 1.0000x reference)
#include <cuda_runtime.h>
#include <math.h>

#define Bb      64
#define Tt      128
#define Dd      768
#define Hh      256
#define NSPANS  8256
#define KTOP    256
#define XST     68          // proj w stride
#define RST     132         // proj xs row-stride
#define SXST    68          // scorer/head xs row-stride
#define PCH     32          // proj k-chunk size

typedef unsigned long long u64;

// ---------------- packed fp32x2 helpers (sm_103a FFMA2 path) ----------------
__device__ __forceinline__ u64 dup2(float a) {
    u64 r; asm("mov.b64 %0, {%1, %2};" : "=l"(r) : "f"(a), "f"(a)); return r;
}
__device__ __forceinline__ void fma2(u64& acc, u64 a, u64 b) {
    asm("fma.rn.f32x2 %0, %1, %2, %0;" : "+l"(acc) : "l"(a), "l"(b));
}
__device__ __forceinline__ void unpack2(float& lo, float& hi, u64 v) {
    asm("mov.b64 {%0, %1}, %2;" : "=f"(lo), "=f"(hi) : "l"(v));
}

// ---------------- device scratch ----------------
__device__ float g_A[Bb*Tt*Hh];
__device__ float g_E[Bb*Tt*Hh];
__device__ float g_scores[Bb*NSPANS];
__device__ float g_inj[Bb*Hh];
__device__ int   g_topidx[Bb*KTOP];
__device__ float g_topscore[Bb*KTOP];
__device__ int   g_sarr[NSPANS];
__device__ int   g_earr[NSPANS];
__device__ u64   g_W1d[Hh*Hh];   // W1 pre-duplicated (w,w) — 512 KB
__device__ u64   g_Wsd[Hh*Hh];   // Wsec pre-duplicated

// ---------------- span index decode ----------------
__global__ void build_span_idx_kernel() {
    int n = blockIdx.x * blockDim.x + threadIdx.x;
    if (n >= NSPANS) return;
    int s = 0, off = 0;
    while (n >= off + (Tt - s)) { off += (Tt - s); s++; }
    g_sarr[n] = s;
    g_earr[n] = s + (n - off);
}

// ---------------- weight duplication prep ----------------
__global__ void wdup_kernel(const float* __restrict__ Ws1, const float* __restrict__ Wsec) {
    int idx = blockIdx.x * blockDim.x + threadIdx.x;   // 65536
    g_W1d[idx] = dup2(Ws1[idx]);
    g_Wsd[idx] = dup2(Wsec[idx]);
}

// ---------------- projections (round-14, unchanged) ----------------
__global__ __launch_bounds__(256)
void proj_kernel(const float* __restrict__ X,
                 const float* __restrict__ Wst, const float* __restrict__ bst,
                 const float* __restrict__ Wen, const float* __restrict__ ben) {
    const float* W    = blockIdx.z ? Wen : Wst;
    const float* bias = blockIdx.z ? ben : bst;
    float*       Out  = blockIdx.z ? g_E : g_A;

    __shared__ float xs[2][PCH * RST];
    __shared__ float wsm[2][PCH * XST];

    const int row0 = blockIdx.y * 128;
    const int col0 = blockIdx.x * 64;
    const int tid  = threadIdx.x;
    const int tx   = tid & 15, ty = tid >> 4;

    const int kq = tid & 7;
    const int rX = tid >> 3;
    const int cq = tid & 15;
    const int kW = tid >> 4;

    const float* Xb = X + (u64)row0 * Dd + 4 * kq;
    const float* Wb = W + col0 + 4 * cq;

    float4 px0 = *(const float4*)(Xb + (u64)(rX)      * Dd);
    float4 px1 = *(const float4*)(Xb + (u64)(rX + 32) * Dd);
    float4 px2 = *(const float4*)(Xb + (u64)(rX + 64) * Dd);
    float4 px3 = *(const float4*)(Xb + (u64)(rX + 96) * Dd);
    float4 pw0 = *(const float4*)(Wb + (u64)kW        * Hh);
    float4 pw1 = *(const float4*)(Wb + (u64)(kW + 16) * Hh);

    {
        float* xd = xs[0];
        xd[(4*kq+0) * RST + rX] = px0.x; xd[(4*kq+1) * RST + rX] = px0.y;
        xd[(4*kq+2) * RST + rX] = px0.z; xd[(4*kq+3) * RST + rX] = px0.w;
        xd[(4*kq+0) * RST + rX+32] = px1.x; xd[(4*kq+1) * RST + rX+32] = px1.y;
        xd[(4*kq+2) * RST + rX+32] = px1.z; xd[(4*kq+3) * RST + rX+32] = px1.w;
        xd[(4*kq+0) * RST + rX+64] = px2.x; xd[(4*kq+1) * RST + rX+64] = px2.y;
        xd[(4*kq+2) * RST + rX+64] = px2.z; xd[(4*kq+3) * RST + rX+64] = px2.w;
        xd[(4*kq+0) * RST + rX+96] = px3.x; xd[(4*kq+1) * RST + rX+96] = px3.y;
        xd[(4*kq+2) * RST + rX+96] = px3.z; xd[(4*kq+3) * RST + rX+96] = px3.w;
        *(float4*)(wsm[0] + kW * XST + 4 * cq)        = pw0;
        *(float4*)(wsm[0] + (kW + 16) * XST + 4 * cq) = pw1;
    }
    __syncthreads();

    u64 acc[4][4] = {};

    #pragma unroll 1
    for (int kc = 0; kc < Dd / PCH; kc++) {
        const int buf = kc & 1;
        if (kc < Dd / PCH - 1) {
            const float* Xn = Xb + (kc + 1) * PCH;
            const float* Wn = Wb + (u64)(kc + 1) * PCH * Hh;
            px0 = *(const float4*)(Xn + (u64)(rX)      * Dd);
            px1 = *(const float4*)(Xn + (u64)(rX + 32) * Dd);
            px2 = *(const float4*)(Xn + (u64)(rX + 64) * Dd);
            px3 = *(const float4*)(Xn + (u64)(rX + 96) * Dd);
            pw0 = *(const float4*)(Wn + (u64)kW        * Hh);
            pw1 = *(const float4*)(Wn + (u64)(kW + 16) * Hh);
        }

        const float* xp = xs[buf] + (ty << 3);
        const float* wp = wsm[buf] + (tx << 2);
        #pragma unroll 8
        for (int k = 0; k < PCH; k++) {
            float4 wv = *(const float4*)(wp + k * XST);
            u64 e0 = dup2(wv.x), e1 = dup2(wv.y), e2 = dup2(wv.z), e3 = dup2(wv.w);
            ulonglong2 p0 = *(const ulonglong2*)(xp + k * RST);
            ulonglong2 p1 = *(const ulonglong2*)(xp + k * RST + 4);
            u64 r0 = p0.x, r1 = p0.y, r2 = p1.x, r3 = p1.y;
            fma2(acc[0][0], r0, e0); fma2(acc[0][1], r0, e1);
            fma2(acc[0][2], r0, e2); fma2(acc[0][3], r0, e3);
            fma2(acc[1][0], r1, e0); fma2(acc[1][1], r1, e1);
            fma2(acc[1][2], r1, e2); fma2(acc[1][3], r1, e3);
            fma2(acc[2][0], r2, e0); fma2(acc[2][1], r2, e1);
            fma2(acc[2][2], r2, e2); fma2(acc[2][3], r2, e3);
            fma2(acc[3][0], r3, e0); fma2(acc[3][1], r3, e1);
            fma2(acc[3][2], r3, e2); fma2(acc[3][3], r3, e3);
        }

        if (kc < Dd / PCH - 1) {
            const int nb = buf ^ 1;
            float* xd = xs[nb];
            xd[(4*kq+0) * RST + rX] = px0.x; xd[(4*kq+1) * RST + rX] = px0.y;
            xd[(4*kq+2) * RST + rX] = px0.z; xd[(4*kq+3) * RST + rX] = px0.w;
            xd[(4*kq+0) * RST + rX+32] = px1.x; xd[(4*kq+1) * RST + rX+32] = px1.y;
            xd[(4*kq+2) * RST + rX+32] = px1.z; xd[(4*kq+3) * RST + rX+32] = px1.w;
            xd[(4*kq+0) * RST + rX+64] = px2.x; xd[(4*kq+1) * RST + rX+64] = px2.y;
            xd[(4*kq+2) * RST + rX+64] = px2.z; xd[(4*kq+3) * RST + rX+64] = px2.w;
            xd[(4*kq+0) * RST + rX+96] = px3.x; xd[(4*kq+1) * RST + rX+96] = px3.y;
            xd[(4*kq+2) * RST + rX+96] = px3.z; xd[(4*kq+3) * RST + rX+96] = px3.w;
            *(float4*)(wsm[nb] + kW * XST + 4 * cq)        = pw0;
            *(float4*)(wsm[nb] + (kW + 16) * XST + 4 * cq) = pw1;
        }
        __syncthreads();
    }

    #pragma unroll
    for (int rp = 0; rp < 4; rp++) {
        int row = row0 + (ty << 3) + 2 * rp;
        #pragma unroll
        for (int c = 0; c < 4; c++) {
            float lo, hi; unpack2(lo, hi, acc[rp][c]);
            int col = col0 + (tx << 2) + c;
            Out[row * Hh + col]       = lo + bias[col];
            Out[(row + 1) * Hh + col] = hi + bias[col];
        }
    }
}

// ---------------- injection projection ----------------
__global__ void inj_kernel(const float* __restrict__ tie,
                           const float* __restrict__ Winj, const float* __restrict__ binj) {
    int b = blockIdx.x;
    int j = threadIdx.x;
    __shared__ float t[128];
    if (j < 128) t[j] = tie[b * 128 + j];
    __syncthreads();
    float acc = binj[j];
    #pragma unroll 8
    for (int k = 0; k < 128; k++) acc = fmaf(t[k], Winj[k * Hh + j], acc);
    g_inj[b * Hh + j] = acc;
}

// ---------------- common smem layout (scorer & head) ----------------
#define SN_BIAS_OFF    (256 * SXST)
#define SN_W2_OFF      (SN_BIAS_OFF + 256)
#define SN_RED_OFF     (SN_W2_OFF + 256)
#define SN_SMEM_FLOATS (SN_RED_OFF + 64 * 65)
static const int SN_SMEM_BYTES = SN_SMEM_FLOATS * 4;   // 88,320 B -> 2 CTAs/SM

// inner body: e0..e3 are pre-duplicated (w,w) operands
#define SC_FMA(E0, E1, E2, E3, AP)                                         \
    {                                                                      \
        ulonglong2 p0 = *(const ulonglong2*)(AP);                          \
        ulonglong2 p1 = *(const ulonglong2*)((AP) + 2);                    \
        ulonglong2 p2 = *(const ulonglong2*)((AP) + 4);                    \
        ulonglong2 p3 = *(const ulonglong2*)((AP) + 6);                    \
        u64 r0 = p0.x, r1 = p0.y, r2 = p1.x, r3 = p1.y;                    \
        u64 r4 = p2.x, r5 = p2.y, r6 = p3.x, r7 = p3.y;                    \
        fma2(acc[0][0], r0, E0); fma2(acc[0][1], r0, E1);                  \
        fma2(acc[0][2], r0, E2); fma2(acc[0][3], r0, E3);                  \
        fma2(acc[1][0], r1, E0); fma2(acc[1][1], r1, E1);                  \
        fma2(acc[1][2], r1, E2); fma2(acc[1][3], r1, E3);                  \
        fma2(acc[2][0], r2, E0); fma2(acc[2][1], r2, E1);                  \
        fma2(acc[2][2], r2, E2); fma2(acc[2][3], r2, E3);                  \
        fma2(acc[3][0], r3, E0); fma2(acc[3][1], r3, E1);                  \
        fma2(acc[3][2], r3, E2); fma2(acc[3][3], r3, E3);                  \
        fma2(acc[4][0], r4, E0); fma2(acc[4][1], r4, E1);                  \
        fma2(acc[4][2], r4, E2); fma2(acc[4][3], r4, E3);                  \
        fma2(acc[5][0], r5, E0); fma2(acc[5][1], r5, E1);                  \
        fma2(acc[5][2], r5, E2); fma2(acc[5][3], r5, E3);                  \
        fma2(acc[6][0], r6, E0); fma2(acc[6][1], r6, E1);                  \
        fma2(acc[6][2], r6, E2); fma2(acc[6][3], r6, E3);                  \
        fma2(acc[7][0], r7, E0); fma2(acc[7][1], r7, E1);                  \
        fma2(acc[7][2], r7, E2); fma2(acc[7][3], r7, E3);                  \
    }

// ---------------- scorer: direct-LDG pre-duplicated weights ----------------
__global__ __launch_bounds__(256, 2)
void scorer_kernel(const float* __restrict__ bs1,
                   const float* __restrict__ Ws2, const float* __restrict__ bs2) {
    extern __shared__ float sm[];
    float* xs   = sm;
    float* bs1c = sm + SN_BIAS_OFF;
    float* w2c  = sm + SN_W2_OFF;
    float* red  = sm + SN_RED_OFF;
    __shared__ int sS[64], sE[64];

    const int b   = blockIdx.y;
    const int n0  = blockIdx.x * 64;
    const int tid = threadIdx.x;
    const int tx  = tid & 63;
    const int ty  = tid >> 6;

    if (tid < 64) {
        sS[tid] = g_sarr[n0 + tid]; sE[tid] = g_earr[n0 + tid];
    }
    bs1c[tid] = bs1[tid];
    w2c[tid]  = Ws2[tid];
    __syncthreads();

    {
        const float* Ab = g_A + b * Tt * Hh + tid;
        const float* Eb = g_E + b * Tt * Hh + tid;
        float* xp = xs + tid * SXST;
        #pragma unroll 4
        for (int r = 0; r < 64; r++) {
            float v = Ab[sS[r] * Hh] + Eb[sE[r] * Hh];
            xp[r] = v > 0.f ? v : 0.f;
        }
    }
    __syncthreads();   // the ONLY mainloop barrier

    // duplicated-weight stream: per k, thread reads 4 u64 = 2 x LDG.128
    const u64* Wg = g_W1d + (tx << 2);
    ulonglong2 pa0 = *(const ulonglong2*)(Wg);
    ulonglong2 pa1 = *(const ulonglong2*)(Wg + 2);
    ulonglong2 pb0 = *(const ulonglong2*)(Wg + 256);
    ulonglong2 pb1 = *(const ulonglong2*)(Wg + 258);

    const float* xp = xs + (ty << 4);
    u64 acc[8][4] = {};

    #pragma unroll 8
    for (int k = 0; k < 256; k++) {
        u64 e0, e1, e2, e3;
        int kp = (k + 2) & 255;        // tail wraps; loads unused, harmless
        const u64* Wn = Wg + (kp << 8);
        if (k & 1) {
            e0 = pb0.x; e1 = pb0.y; e2 = pb1.x; e3 = pb1.y;
            pb0 = *(const ulonglong2*)(Wn);
            pb1 = *(const ulonglong2*)(Wn + 2);
        } else {
            e0 = pa0.x; e1 = pa0.y; e2 = pa1.x; e3 = pa1.y;
            pa0 = *(const ulonglong2*)(Wn);
            pa1 = *(const ulonglong2*)(Wn + 2);
        }
        const u64* ap = (const u64*)(xp + k * SXST);
        SC_FMA(e0, e1, e2, e3, ap);
    }

    float scacc[16];
    #pragma unroll
    for (int i = 0; i < 16; i++) scacc[i] = 0.f;
    #pragma unroll
    for (int rp = 0; rp < 8; rp++) {
        #pragma unroll
        for (int c = 0; c < 4; c++) {
            float lo, hi; unpack2(lo, hi, acc[rp][c]);
            int cb = (tx << 2) + c;
            float h0 = lo + bs1c[cb];
            if (h0 > 0.f) scacc[2 * rp]     = fmaf(h0, w2c[cb], scacc[2 * rp]);
            float h1 = hi + bs1c[cb];
            if (h1 > 0.f) scacc[2 * rp + 1] = fmaf(h1, w2c[cb], scacc[2 * rp + 1]);
        }
    }

    #pragma unroll
    for (int i = 0; i < 16; i++) red[((ty << 4) + i) * 65 + tx] = scacc[i];
    __syncthreads();
    if (tid < 64) {
        float ssum = bs2[0];
        const float* rp = red + tid * 65;
        #pragma unroll
        for (int t = 0; t < 64; t++) ssum += rp[t];
        g_scores[b * NSPANS + n0 + tid] = ssum;
    }
}

// ---------------- block inclusive scan (256 threads) ----------------
__device__ __forceinline__ int block_incl_scan(int v, int tid, int* wsums) {
    __syncthreads();
    int lane = tid & 31, wid = tid >> 5;
    #pragma unroll
    for (int o = 1; o < 32; o <<= 1) {
        int n = __shfl_up_sync(0xffffffffu, v, o);
        if (lane >= o) v += n;
    }
    if (lane == 31) wsums[wid] = v;
    __syncthreads();
    if (tid == 0) {
        int s = 0;
        #pragma unroll
        for (int w = 0; w < 8; w++) { int x = wsums[w]; wsums[w] = s; s += x; }
    }
    __syncthreads();
    return v + wsums[wid];
}

// ---------------- per-batch radix top-k (round-13, unchanged) ----------------
__global__ void topk_kernel(const int* __restrict__ mask) {
    const int b   = blockIdx.x;
    const int tid = threadIdx.x;
    __shared__ unsigned keys[NSPANS];
    __shared__ int hist[256];
    __shared__ unsigned sh_prefix;
    __shared__ int sh_kk;
    __shared__ int wsums[8];

    const int* mb = mask + b * Tt;
    for (int i = tid; i < NSPANS; i += 256) {
        int s = g_sarr[i], e = g_earr[i];
        float v = (mb[s] != 0 && mb[e] != 0) ? g_scores[b * NSPANS + i]
                                             : __int_as_float(0xff800000);
        unsigned u = __float_as_uint(v);
        keys[i] = (u & 0x80000000u) ? ~u : (u | 0x80000000u);
    }

    unsigned prefix = 0;
    int kk = KTOP;
    for (int level = 3; level >= 0; level--) {
        hist[tid] = 0;
        __syncthreads();
        const unsigned himask = (level == 3) ? 0u : (0xFFFFFFFFu << ((level + 1) * 8));
        for (int i = tid; i < NSPANS; i += 256) {
            unsigned kv = keys[i];
            if ((kv & himask) == (prefix & himask))
                atomicAdd(&hist[(kv >> (level * 8)) & 255], 1);
        }
        __syncthreads();
        int bucket = 255 - tid;
        int v = hist[bucket];
        int S = block_incl_scan(v, tid, wsums);
        if (S >= kk && S - v < kk) {
            sh_prefix = prefix | ((unsigned)bucket << (level * 8));
            sh_kk = kk - (S - v);
        }
        __syncthreads();
        prefix = sh_prefix;
        kk = sh_kk;
        __syncthreads();
    }

    const unsigned Kstar = prefix;
    const int CH = (NSPANS + 255) / 256;
    int lo = tid * CH; if (lo > NSPANS) lo = NSPANS;
    int hi = lo + CH;  if (hi > NSPANS) hi = NSPANS;

    int cgt = 0, ceq = 0;
    for (int i = lo; i < hi; i++) {
        unsigned kv = keys[i];
        cgt += (kv > Kstar);
        ceq += (kv == Kstar);
    }
    int Sg = block_incl_scan(cgt, tid, wsums);
    int Se = block_incl_scan(ceq, tid, wsums);
    int gtb = Sg - cgt, eqb = Se - ceq;

    for (int i = lo; i < hi; i++) {
        unsigned kv = keys[i];
        bool isgt = (kv > Kstar);
        bool iseq = (kv == Kstar);
        if (isgt || (iseq && eqb < kk)) {
            int eqt = eqb < kk ? eqb : kk;
            int pos = gtb + eqt;
            unsigned u = (kv & 0x80000000u) ? (kv & 0x7FFFFFFFu) : ~kv;
            g_topidx[b * KTOP + pos]   = i;
            g_topscore[b * KTOP + pos] = __uint_as_float(u);
        }
        gtb += isgt;
        eqb += iseq;
    }
}

// ---------------- head: direct-LDG pre-duplicated weights ----------------
__global__ __launch_bounds__(256, 2)
void head_kernel(const float* __restrict__ bsec,
                 const float* __restrict__ Wpred, const float* __restrict__ bpred,
                 const int* __restrict__ mask, float* __restrict__ out) {
    extern __shared__ float sm[];
    float* xs  = sm;
    float* bc  = sm + SN_BIAS_OFF;
    float* wpc = sm + SN_W2_OFF;
    float* red = sm + SN_RED_OFF;
    __shared__ int sS[64], sE[64];
    __shared__ float sMask[64], sScore[64];

    const int b   = blockIdx.y;
    const int k0  = blockIdx.x * 64;
    const int tid = threadIdx.x;
    const int tx  = tid & 63;
    const int ty  = tid >> 6;

    if (tid < 64) {
        int n = g_topidx[b * KTOP + k0 + tid];
        int s = g_sarr[n], e = g_earr[n];
        sS[tid] = s; sE[tid] = e;
        sMask[tid] = (mask[b * Tt + s] != 0 && mask[b * Tt + e] != 0) ? 1.f : 0.f;
        float sc = g_topscore[b * KTOP + k0 + tid];
        sScore[tid] = isinf(sc) ? -1.f : sc;
    }
    bc[tid]  = bsec[tid] + g_inj[b * Hh + tid];
    wpc[tid] = Wpred[tid];
    __syncthreads();

    {
        const float* Ab = g_A + b * Tt * Hh + tid;
        const float* Eb = g_E + b * Tt * Hh + tid;
        float* xp = xs + tid * SXST;
        #pragma unroll 4
        for (int r = 0; r < 64; r++)
            xp[r] = Ab[sS[r] * Hh] + Eb[sE[r] * Hh];   // no relu
    }
    __syncthreads();

    const u64* Wg = g_Wsd + (tx << 2);
    ulonglong2 pa0 = *(const ulonglong2*)(Wg);
    ulonglong2 pa1 = *(const ulonglong2*)(Wg + 2);
    ulonglong2 pb0 = *(const ulonglong2*)(Wg + 256);
    ulonglong2 pb1 = *(const ulonglong2*)(Wg + 258);

    const float* xp = xs + (ty << 4);
    u64 acc[8][4] = {};

    #pragma unroll 8
    for (int k = 0; k < 256; k++) {
        u64 e0, e1, e2, e3;
        int kp = (k + 2) & 255;
        const u64* Wn = Wg + (kp << 8);
        if (k & 1) {
            e0 = pb0.x; e1 = pb0.y; e2 = pb1.x; e3 = pb1.y;
            pb0 = *(const ulonglong2*)(Wn);
            pb1 = *(const ulonglong2*)(Wn + 2);
        } else {
            e0 = pa0.x; e1 = pa0.y; e2 = pa1.x; e3 = pa1.y;
            pa0 = *(const ulonglong2*)(Wn);
            pa1 = *(const ulonglong2*)(Wn + 2);
        }
        const u64* ap = (const u64*)(xp + k * SXST);
        SC_FMA(e0, e1, e2, e3, ap);
    }

    float scacc[16];
    #pragma unroll
    for (int i = 0; i < 16; i++) scacc[i] = 0.f;
    #pragma unroll
    for (int rp = 0; rp < 8; rp++) {
        #pragma unroll
        for (int c = 0; c < 4; c++) {
            float lo, hi; unpack2(lo, hi, acc[rp][c]);
            int cb = (tx << 2) + c;
            float h0 = lo + bc[cb];
            if (h0 > 0.f) scacc[2 * rp]     = fmaf(h0, wpc[cb], scacc[2 * rp]);
            float h1 = hi + bc[cb];
            if (h1 > 0.f) scacc[2 * rp + 1] = fmaf(h1, wpc[cb], scacc[2 * rp + 1]);
        }
    }

    #pragma unroll
    for (int i = 0; i < 16; i++) red[((ty << 4) + i) * 65 + tx] = scacc[i];
    __syncthreads();
    if (tid < 64) {
        float ssum = bpred[0] + sScore[tid];
        const float* rp = red + tid * 65;
        #pragma unroll
        for (int t = 0; t < 64; t++) ssum += rp[t];
        float p = 1.f / (1.f + expf(-ssum));
        out[b * KTOP + k0 + tid] = p * sMask[tid];
    }
}

// ---------------- launch ----------------
extern "C" void kernel_launch(void* const* d_in, const int* in_sizes, int n_in,
                              void* d_out, int out_size) {
    const float* inputs   = (const float*)d_in[0];
    const int*   in_mask  = (const int*)  d_in[1];
    const float* tie      = (const float*)d_in[2];
    const float* W_start  = (const float*)d_in[3];
    const float* b_start  = (const float*)d_in[4];
    const float* W_end    = (const float*)d_in[5];
    const float* b_end    = (const float*)d_in[6];
    const float* W_s1     = (const float*)d_in[7];
    const float* b_s1     = (const float*)d_in[8];
    const float* W_s2     = (const float*)d_in[9];
    const float* b_s2     = (const float*)d_in[10];
    const float* W_inj    = (const float*)d_in[11];
    const float* b_inj    = (const float*)d_in[12];
    const float* W_sec    = (const float*)d_in[13];
    const float* b_sec    = (const float*)d_in[14];
    const float* W_pred   = (const float*)d_in[15];
    const float* b_pred   = (const float*)d_in[16];
    float* out = (float*)d_out;

    cudaFuncSetAttribute(scorer_kernel, cudaFuncAttributeMaxDynamicSharedMemorySize, SN_SMEM_BYTES);
    cudaFuncSetAttribute(head_kernel,   cudaFuncAttributeMaxDynamicSharedMemorySize, SN_SMEM_BYTES);

    build_span_idx_kernel<<<(NSPANS + 255) / 256, 256>>>();
    wdup_kernel<<<Hh * Hh / 256, 256>>>(W_s1, W_sec);
    proj_kernel<<<dim3(Hh / 64, (Bb * Tt) / 128, 2), 256>>>(inputs, W_start, b_start, W_end, b_end);
    inj_kernel<<<Bb, 256>>>(tie, W_inj, b_inj);
    scorer_kernel<<<dim3(NSPANS / 64, Bb), 256, SN_SMEM_BYTES>>>(b_s1, W_s2, b_s2);
    topk_kernel<<<Bb, 256>>>(in_mask);
    head_kernel<<<dim3(KTOP / 64, Bb), 256, SN_SMEM_BYTES>>>(b_sec, W_pred, b_pred, in_mask, out);
}